// round 8
// baseline (speedup 1.0000x reference)
#include <cuda_runtime.h>
#include <cuda_fp16.h>
#include <cuda_bf16.h>
#include <math.h>

// Problem constants
#define B     256
#define V     100
#define C     40
#define E     128
#define H     100
#define G4    400      // 4*H
#define M_TOT 32768    // B*E

// ---------------- device scratch ----------------
__device__ int   g_last[B];
__device__ __align__(16) float g_xseq[B * V * E];    // A[32768][100]
__device__ __align__(16) float g_xpart[M_TOT * G4];  // x @ W_ih^T + biases
__device__ float g_trueh[B * E];

// ---------------- tf32 helpers ----------------
__device__ __forceinline__ unsigned f2tf32(float f) {
    unsigned r;
    asm("cvt.rna.tf32.f32 %0, %1;" : "=r"(r) : "f"(f));
    return r;
}
__device__ __forceinline__ void split_tf32(float a, unsigned& hi, unsigned& lo) {
    hi = f2tf32(a);
    lo = f2tf32(a - __uint_as_float(hi));
}
__device__ __forceinline__ void mma8(float* d, const unsigned* a,
                                     unsigned b0, unsigned b1) {
    asm("mma.sync.aligned.m16n8k8.row.col.f32.tf32.tf32.f32 "
        "{%0,%1,%2,%3},{%4,%5,%6,%7},{%8,%9},{%0,%1,%2,%3};"
        : "+f"(d[0]), "+f"(d[1]), "+f"(d[2]), "+f"(d[3])
        : "r"(a[0]), "r"(a[1]), "r"(a[2]), "r"(a[3]), "r"(b0), "r"(b1));
}

// ---------------- K0: last visit index per batch row ----------------
__global__ void k_last(const float* __restrict__ mask) {
    __shared__ int red[128];
    int b = blockIdx.x, tid = threadIdx.x;
    int best = -1;
    if (tid < V) {
        const float* mp = mask + (b * V + tid) * C;
        bool has = false;
        #pragma unroll 8
        for (int c = 0; c < C; c++) has |= (mp[c] != 0.f);
        if (has) best = tid;
    }
    red[tid] = best;
    __syncthreads();
    #pragma unroll
    for (int s = 64; s > 0; s >>= 1) {
        if (tid < s) red[tid] = max(red[tid], red[tid + s]);
        __syncthreads();
    }
    if (tid == 0) g_last[b] = (red[0] < 0) ? (V - 1) : red[0];
}

// ---------------- K1: masked embedding sum (+inline dtype detect) ----------
__global__ void k_embed(const int* __restrict__ diag,
                        const float* __restrict__ mask,
                        const float* __restrict__ table) {
    int flag = 0;
    if (threadIdx.x < 64) flag = diag[2 * threadIdx.x + 1];
    int is64 = __syncthreads_or(flag != 0) ? 0 : 1;

    int p    = blockIdx.x * 8 + (threadIdx.x >> 5);   // (b*V + v)
    int lane = threadIdx.x & 31;
    const float4* tab4 = (const float4*)table;
    float4 acc = make_float4(0.f, 0.f, 0.f, 0.f);
    int base = p * C;
    #pragma unroll 4
    for (int c = 0; c < C; c++) {
        int idx = base + c;
        float m = mask[idx];
        int code = diag[idx << is64];
        if (m != 0.f) {
            float4 t = tab4[code * 32 + lane];
            acc.x += t.x * m; acc.y += t.y * m; acc.z += t.z * m; acc.w += t.w * m;
        }
    }
    ((float4*)g_xseq)[p * 32 + lane] = acc;
}

// ---------------- K2: 3xTF32 tensor GEMM ----------------
#define BMg 128
#define BNg 80
#define SST 36

__global__ void __launch_bounds__(256, 2) k_gemm(const float* __restrict__ W,
                                                 const float* __restrict__ bih,
                                                 const float* __restrict__ bhh) {
    __shared__ float    As[BMg * SST];
    __shared__ unsigned Wh[BNg * SST];
    __shared__ unsigned Wl[BNg * SST];

    int tid = threadIdx.x;
    int wid = tid >> 5, lane = tid & 31;
    int wm = wid & 3, wn = wid >> 2;
    int g = lane >> 2, t = lane & 3;
    int m0 = blockIdx.x * BMg;
    int n0 = blockIdx.y * BNg;

    float d[2][5][4];
    #pragma unroll
    for (int ni = 0; ni < 5; ni++) {
        int cc = n0 + wn * 40 + ni * 8 + 2 * t;
        float b0 = bih[cc] + bhh[cc];
        float b1 = bih[cc + 1] + bhh[cc + 1];
        #pragma unroll
        for (int mi = 0; mi < 2; mi++) {
            d[mi][ni][0] = b0; d[mi][ni][1] = b1;
            d[mi][ni][2] = b0; d[mi][ni][3] = b1;
        }
    }

    #pragma unroll 1
    for (int kc = 0; kc < 4; kc++) {
        int k0 = kc * 32;
        #pragma unroll
        for (int i = 0; i < 16; i++) {
            int li = i * 256 + tid;
            int m = li >> 5, k = li & 31;
            As[m * SST + k] = (k0 + k < 100) ? g_xseq[(m0 + m) * 100 + k0 + k] : 0.f;
        }
        #pragma unroll
        for (int i = 0; i < 10; i++) {
            int li = i * 256 + tid;
            int n = li >> 5, k = li & 31;
            float w = (k0 + k < 100) ? W[(n0 + n) * 100 + k0 + k] : 0.f;
            unsigned hi, lo;
            split_tf32(w, hi, lo);
            Wh[n * SST + k] = hi;
            Wl[n * SST + k] = lo;
        }
        __syncthreads();

        int ns = (kc == 3) ? 1 : 4;
        #pragma unroll
        for (int s = 0; s < 4; s++) {
            if (s >= ns) break;
            unsigned ah[2][4], al[2][4];
            #pragma unroll
            for (int mi = 0; mi < 2; mi++) {
                int r = (wm * 32 + mi * 16 + g) * SST + s * 8 + t;
                split_tf32(As[r],               ah[mi][0], al[mi][0]);
                split_tf32(As[r + 8 * SST],     ah[mi][1], al[mi][1]);
                split_tf32(As[r + 4],           ah[mi][2], al[mi][2]);
                split_tf32(As[r + 8 * SST + 4], ah[mi][3], al[mi][3]);
            }
            #pragma unroll
            for (int ni = 0; ni < 5; ni++) {
                int rb = (wn * 40 + ni * 8 + g) * SST + s * 8 + t;
                unsigned bh0 = Wh[rb], bh1 = Wh[rb + 4];
                unsigned bl0 = Wl[rb], bl1 = Wl[rb + 4];
                #pragma unroll
                for (int mi = 0; mi < 2; mi++) {
                    mma8(d[mi][ni], ah[mi], bh0, bh1);
                    mma8(d[mi][ni], ah[mi], bl0, bl1);
                    mma8(d[mi][ni], al[mi], bh0, bh1);
                }
            }
        }
        __syncthreads();
    }

    #pragma unroll
    for (int mi = 0; mi < 2; mi++) {
        int r = m0 + wm * 32 + mi * 16 + g;
        #pragma unroll
        for (int ni = 0; ni < 5; ni++) {
            int cc = n0 + wn * 40 + ni * 8 + 2 * t;
            *(float2*)&g_xpart[r * G4 + cc]       = make_float2(d[mi][ni][0], d[mi][ni][1]);
            *(float2*)&g_xpart[(r + 8) * G4 + cc] = make_float2(d[mi][ni][2], d[mi][ni][3]);
        }
    }
}

// ---------------- K3: warp-quad LSTM recurrence, one CTA per embed-row ----
// 416 thr = 13 full warps. Unit u = tid>>2, gate type gt = tid&3 (i,f,g,o).
// All 4 gates of a unit sit in one lane-quad -> gate exchange via shfl,
// cell update computed redundantly by the quad (bitwise identical).
// h double-buffered in smem -> exactly ONE __syncthreads per step.
__device__ __forceinline__ float sigf(float x) {
    return 1.f / (1.f + __expf(-x));
}
__device__ __forceinline__ float tanhfast(float x) {
    x = fminf(fmaxf(x, -15.f), 15.f);
    float e = __expf(2.f * x);
    return (e - 1.f) / (e + 1.f);
}

__global__ void __launch_bounds__(416, 1) k_rec(const float* __restrict__ Whh) {
    __shared__ __align__(16) __half hbuf[2][104];   // h[0..99] + zero pad
    __shared__ int last_s[B];

    int tid = threadIdx.x;
    int e   = blockIdx.x;
    int u   = tid >> 2;          // unit 0..103 (valid < 100)
    int gt  = tid & 3;           // 0=i 1=f 2=g 3=o
    int lane = tid & 31;
    int qbase = lane & ~3;       // first lane of this quad
    bool valid = (u < H);
    int uc = valid ? u : (H - 1);
    int grow = gt * H + uc;      // gate row in [0,400)

    // 52 half2 weight regs for W_hh[grow][*] (zeros if invalid/pad)
    __half2 w2[52];
    #pragma unroll
    for (int j = 0; j < 50; j++) {
        float lo = 0.f, hi = 0.f;
        if (valid) {
            lo = Whh[grow * 100 + 2 * j];
            hi = Whh[grow * 100 + 2 * j + 1];
        }
        w2[j] = __floats2half2_rn(lo, hi);
    }
    w2[50] = __floats2half2_rn(0.f, 0.f);
    w2[51] = __floats2half2_rn(0.f, 0.f);

    for (int i = tid; i < B; i += 416) last_s[i] = g_last[i];
    if (tid < 104) {
        hbuf[0][tid] = __float2half_rn(0.f);
        hbuf[1][tid] = __float2half_rn(0.f);
    }
    float c = 0.f;
    __syncthreads();

    const float* xp = g_xpart + e * G4 + grow;   // step stride = E*G4
    float* th = g_trueh + e;

    float xv_next = __ldg(xp);                   // prefetch t=0

    int p = 0;
    #pragma unroll 1
    for (int t = 0; t < B; t++) {
        float xv = xv_next;
        int tn = (t + 1 < B) ? (t + 1) : (B - 1);
        xv_next = __ldg(xp + tn * (E * G4));

        const float4* hvec = (const float4*)hbuf[p];
        __half2 a0 = __floats2half2_rn(0.f, 0.f), a1 = a0, a2 = a0, a3 = a0;
        #pragma unroll
        for (int j = 0; j < 13; j++) {
            float4 hv = hvec[j];
            a0 = __hfma2(w2[4 * j + 0], *(__half2*)&hv.x, a0);
            a1 = __hfma2(w2[4 * j + 1], *(__half2*)&hv.y, a1);
            a2 = __hfma2(w2[4 * j + 2], *(__half2*)&hv.z, a2);
            a3 = __hfma2(w2[4 * j + 3], *(__half2*)&hv.w, a3);
        }
        float2 f0 = __half22float2(a0);
        float2 f1 = __half22float2(a1);
        float2 f2 = __half22float2(a2);
        float2 f3 = __half22float2(a3);
        float dot = ((f0.x + f0.y) + (f1.x + f1.y)) +
                    ((f2.x + f2.y) + (f3.x + f3.y));

        float pre = dot + xv;
        float a = (gt == 2) ? tanhfast(pre) : sigf(pre);

        // gather the quad's four activated gates
        float iv = __shfl_sync(0xFFFFFFFFu, a, qbase + 0);
        float fv = __shfl_sync(0xFFFFFFFFu, a, qbase + 1);
        float gv = __shfl_sync(0xFFFFFFFFu, a, qbase + 2);
        float ov = __shfl_sync(0xFFFFFFFFu, a, qbase + 3);

        c = fv * c + iv * gv;
        float hval = ov * tanhfast(c);

        if (gt == 0 && valid) {
            hbuf[p ^ 1][u] = __float2half_rn(hval);
            if (u == last_s[t]) th[t * E] = hval;
        }
        __syncthreads();
        p ^= 1;
    }
}

// ---------------- K4: final FC + sigmoid ----------------
__global__ void k_fc(const float* __restrict__ fcw,
                     const float* __restrict__ fcb,
                     float* __restrict__ out) {
    int warp = (blockIdx.x * blockDim.x + threadIdx.x) >> 5;
    int lane = threadIdx.x & 31;
    if (warp >= B) return;
    const float* th = g_trueh + warp * E;
    float acc = 0.f;
    #pragma unroll
    for (int k = 0; k < 4; k++) acc += th[lane + 32 * k] * fcw[lane + 32 * k];
    #pragma unroll
    for (int s = 16; s > 0; s >>= 1) acc += __shfl_down_sync(0xFFFFFFFFu, acc, s);
    if (lane == 0) out[warp] = 1.f / (1.f + __expf(-(acc + fcb[0])));
}

// ---------------- launcher: kernel launches ONLY ----------------
extern "C" void kernel_launch(void* const* d_in, const int* in_sizes, int n_in,
                              void* d_out, int out_size) {
    const int*   diag = (const int*)d_in[0];
    const float* mask = (const float*)d_in[1];
    const float* tab  = (const float*)d_in[2];
    const float* Wih  = (const float*)d_in[3];
    const float* Whh  = (const float*)d_in[4];
    const float* bih  = (const float*)d_in[5];
    const float* bhh  = (const float*)d_in[6];
    const float* fcw  = (const float*)d_in[7];
    const float* fcb  = (const float*)d_in[8];
    float* out = (float*)d_out;

    (void)in_sizes; (void)n_in; (void)out_size;

    k_last<<<B, 128>>>(mask);
    k_embed<<<(B * V) / 8, 256>>>(diag, mask, tab);
    k_gemm<<<dim3(M_TOT / BMg, G4 / BNg), 256>>>(Wih, bih, bhh);
    k_rec<<<E, 416>>>(Whh);
    k_fc<<<32, 256>>>(fcw, fcb, out);
}

// round 9
// speedup vs baseline: 1.3917x; 1.3917x over previous
#include <cuda_runtime.h>
#include <cuda_fp16.h>
#include <cuda_bf16.h>
#include <math.h>

// Problem constants
#define B     256
#define V     100
#define C     40
#define E     128
#define H     100
#define G4    400      // 4*H
#define M_TOT 32768    // B*E

// ---------------- device scratch ----------------
__device__ int   g_last[B];
__device__ __align__(16) float g_xseq[B * V * E];    // A[32768][100]
__device__ __align__(16) float g_xpart[M_TOT * G4];  // x @ W_ih^T + biases
__device__ float g_trueh[B * E];

// ---------------- helpers ----------------
__device__ __forceinline__ unsigned f2tf32(float f) {
    unsigned r;
    asm("cvt.rna.tf32.f32 %0, %1;" : "=r"(r) : "f"(f));
    return r;
}
__device__ __forceinline__ void mma8(float* d, const unsigned* a,
                                     unsigned b0, unsigned b1) {
    asm("mma.sync.aligned.m16n8k8.row.col.f32.tf32.tf32.f32 "
        "{%0,%1,%2,%3},{%4,%5,%6,%7},{%8,%9},{%0,%1,%2,%3};"
        : "+f"(d[0]), "+f"(d[1]), "+f"(d[2]), "+f"(d[3])
        : "r"(a[0]), "r"(a[1]), "r"(a[2]), "r"(a[3]), "r"(b0), "r"(b1));
}
__device__ __forceinline__ float tanhapx(float x) {
    float r;
    asm("tanh.approx.f32 %0, %1;" : "=f"(r) : "f"(x));
    return r;
}
__device__ __forceinline__ float sigt(float x) {
    return fmaf(0.5f, tanhapx(0.5f * x), 0.5f);
}

// ---------------- K0: last visit index per batch row ----------------
__global__ void k_last(const float* __restrict__ mask) {
    __shared__ int red[128];
    int b = blockIdx.x, tid = threadIdx.x;
    int best = -1;
    if (tid < V) {
        const float* mp = mask + (b * V + tid) * C;
        bool has = false;
        #pragma unroll 8
        for (int c = 0; c < C; c++) has |= (mp[c] != 0.f);
        if (has) best = tid;
    }
    red[tid] = best;
    __syncthreads();
    #pragma unroll
    for (int s = 64; s > 0; s >>= 1) {
        if (tid < s) red[tid] = max(red[tid], red[tid + s]);
        __syncthreads();
    }
    if (tid == 0) g_last[b] = (red[0] < 0) ? (V - 1) : red[0];
}

// ---------------- K1: masked embedding sum, branchless ----------------
// One warp per (b,v); lane holds 4 of 128 embed dims as float4.
// mask loaded as float4 per 4-code group; 4 gathers in flight (MLP 4).
__global__ void k_embed(const int* __restrict__ diag,
                        const float* __restrict__ mask,
                        const float* __restrict__ table) {
    int flag = 0;
    if (threadIdx.x < 64) flag = diag[2 * threadIdx.x + 1];
    int is64 = __syncthreads_or(flag != 0) ? 0 : 1;

    int p    = blockIdx.x * 8 + (threadIdx.x >> 5);   // (b*V + v)
    int lane = threadIdx.x & 31;
    const float4* tab4 = (const float4*)table;
    float4 acc = make_float4(0.f, 0.f, 0.f, 0.f);
    int base = p * C;
    #pragma unroll
    for (int c4 = 0; c4 < C / 4; c4++) {
        float4 m4 = *(const float4*)(mask + base + c4 * 4);
        int code[4];
        #pragma unroll
        for (int q = 0; q < 4; q++)
            code[q] = diag[(base + c4 * 4 + q) << is64];
        float mm[4] = {m4.x, m4.y, m4.z, m4.w};
        #pragma unroll
        for (int q = 0; q < 4; q++) {
            float4 t = tab4[code[q] * 32 + lane];
            acc.x += t.x * mm[q]; acc.y += t.y * mm[q];
            acc.z += t.z * mm[q]; acc.w += t.w * mm[q];
        }
    }
    ((float4*)g_xseq)[p * 32 + lane] = acc;
}

// ---------------- K2: single-TF32 tensor GEMM ----------------
// x_part[32768,400] = A[32768,100] @ W[400,100]^T + (b_ih + b_hh)
// CTA 256 thr (8 warps 4m x 2n), tile 128m x 80n. tf32 converted at store.
#define BMg 128
#define BNg 80
#define SST 36

__global__ void __launch_bounds__(256, 2) k_gemm(const float* __restrict__ W,
                                                 const float* __restrict__ bih,
                                                 const float* __restrict__ bhh) {
    __shared__ unsigned As[BMg * SST];   // tf32 A tile [m][k]
    __shared__ unsigned Ws[BNg * SST];   // tf32 W tile [n][k]

    int tid = threadIdx.x;
    int wid = tid >> 5, lane = tid & 31;
    int wm = wid & 3, wn = wid >> 2;
    int g = lane >> 2, t = lane & 3;
    int m0 = blockIdx.x * BMg;
    int n0 = blockIdx.y * BNg;

    float d[2][5][4];
    #pragma unroll
    for (int ni = 0; ni < 5; ni++) {
        int cc = n0 + wn * 40 + ni * 8 + 2 * t;
        float b0 = bih[cc] + bhh[cc];
        float b1 = bih[cc + 1] + bhh[cc + 1];
        #pragma unroll
        for (int mi = 0; mi < 2; mi++) {
            d[mi][ni][0] = b0; d[mi][ni][1] = b1;
            d[mi][ni][2] = b0; d[mi][ni][3] = b1;
        }
    }

    #pragma unroll 1
    for (int kc = 0; kc < 4; kc++) {
        int k0 = kc * 32;
        #pragma unroll
        for (int i = 0; i < 16; i++) {
            int li = i * 256 + tid;
            int m = li >> 5, k = li & 31;
            float v = (k0 + k < 100) ? g_xseq[(m0 + m) * 100 + k0 + k] : 0.f;
            As[m * SST + k] = f2tf32(v);
        }
        #pragma unroll
        for (int i = 0; i < 10; i++) {
            int li = i * 256 + tid;
            int n = li >> 5, k = li & 31;
            float w = (k0 + k < 100) ? W[(n0 + n) * 100 + k0 + k] : 0.f;
            Ws[n * SST + k] = f2tf32(w);
        }
        __syncthreads();

        int ns = (kc == 3) ? 1 : 4;      // last chunk covers k 96..99 only
        #pragma unroll
        for (int s = 0; s < 4; s++) {
            if (s >= ns) break;
            unsigned a[2][4];
            #pragma unroll
            for (int mi = 0; mi < 2; mi++) {
                int r = (wm * 32 + mi * 16 + g) * SST + s * 8 + t;
                a[mi][0] = As[r];
                a[mi][1] = As[r + 8 * SST];
                a[mi][2] = As[r + 4];
                a[mi][3] = As[r + 8 * SST + 4];
            }
            #pragma unroll
            for (int ni = 0; ni < 5; ni++) {
                int rb = (wn * 40 + ni * 8 + g) * SST + s * 8 + t;
                unsigned b0 = Ws[rb], b1 = Ws[rb + 4];
                #pragma unroll
                for (int mi = 0; mi < 2; mi++)
                    mma8(d[mi][ni], a[mi], b0, b1);
            }
        }
        __syncthreads();
    }

    #pragma unroll
    for (int mi = 0; mi < 2; mi++) {
        int r = m0 + wm * 32 + mi * 16 + g;
        #pragma unroll
        for (int ni = 0; ni < 5; ni++) {
            int cc = n0 + wn * 40 + ni * 8 + 2 * t;
            *(float2*)&g_xpart[r * G4 + cc]       = make_float2(d[mi][ni][0], d[mi][ni][1]);
            *(float2*)&g_xpart[(r + 8) * G4 + cc] = make_float2(d[mi][ni][2], d[mi][ni][3]);
        }
    }
}

// ---------------- K3: fp16 recurrence (R6 structure + HW tanh) ----------
// 416 thr, 1 thread per gate. W_hh row as 52 half2 regs; h fp16 in smem via
// LDS.128; 2-phase with gates smem + 2 barriers (measured best structure).
__global__ void __launch_bounds__(416, 1) k_rec(const float* __restrict__ Whh) {
    __shared__ __align__(16) __half h_h[104];   // h[0..99] + zero pad
    __shared__ float gates_s[G4];
    __shared__ int   last_s[B];

    int tid = threadIdx.x;
    int e   = blockIdx.x;
    int g   = tid;                        // gate index (valid < 400)
    int gc  = (g < G4) ? g : (G4 - 1);    // clamped for safe gmem addressing

    __half2 w2[52];
    #pragma unroll
    for (int j = 0; j < 50; j++) {
        float lo = 0.f, hi = 0.f;
        if (g < G4) {
            lo = Whh[g * 100 + 2 * j];
            hi = Whh[g * 100 + 2 * j + 1];
        }
        w2[j] = __floats2half2_rn(lo, hi);
    }
    w2[50] = __floats2half2_rn(0.f, 0.f);
    w2[51] = __floats2half2_rn(0.f, 0.f);

    for (int i = tid; i < B; i += 416) last_s[i] = g_last[i];
    if (tid < 104) h_h[tid] = __float2half_rn(0.f);
    float c = 0.f;
    __syncthreads();

    const float* xp = g_xpart + e * G4 + gc;  // step stride = E*G4
    float* th = g_trueh + e;
    const float4* hvec = (const float4*)h_h;

    float xv_next = __ldg(xp);                // prefetch t=0 (branchless)

    #pragma unroll 1
    for (int t = 0; t < B; t++) {
        float xv = xv_next;
        int tn = (t + 1 < B) ? (t + 1) : (B - 1);
        xv_next = __ldg(xp + tn * (E * G4));

        __half2 a0 = __floats2half2_rn(0.f, 0.f), a1 = a0, a2 = a0, a3 = a0;
        #pragma unroll
        for (int j = 0; j < 13; j++) {
            float4 hv = hvec[j];
            a0 = __hfma2(w2[4 * j + 0], *(__half2*)&hv.x, a0);
            a1 = __hfma2(w2[4 * j + 1], *(__half2*)&hv.y, a1);
            a2 = __hfma2(w2[4 * j + 2], *(__half2*)&hv.z, a2);
            a3 = __hfma2(w2[4 * j + 3], *(__half2*)&hv.w, a3);
        }
        float2 f0 = __half22float2(a0);
        float2 f1 = __half22float2(a1);
        float2 f2 = __half22float2(a2);
        float2 f3 = __half22float2(a3);
        float dot = ((f0.x + f0.y) + (f1.x + f1.y)) +
                    ((f2.x + f2.y) + (f3.x + f3.y));

        if (g < G4) {
            float pre = dot + xv;
            float a = (g < 200 || g >= 300) ? sigt(pre) : tanhapx(pre);
            gates_s[g] = a;
        }
        __syncthreads();

        if (tid < H) {
            float iv = gates_s[tid];
            float fv = gates_s[H + tid];
            float gv = gates_s[2 * H + tid];
            float ov = gates_s[3 * H + tid];
            c = fv * c + iv * gv;
            float hval = ov * tanhapx(c);
            h_h[tid] = __float2half_rn(hval);
            if (tid == last_s[t]) th[t * E] = hval;
        }
        __syncthreads();
    }
}

// ---------------- K4: final FC + sigmoid ----------------
__global__ void k_fc(const float* __restrict__ fcw,
                     const float* __restrict__ fcb,
                     float* __restrict__ out) {
    int warp = (blockIdx.x * blockDim.x + threadIdx.x) >> 5;
    int lane = threadIdx.x & 31;
    if (warp >= B) return;
    const float* th = g_trueh + warp * E;
    float acc = 0.f;
    #pragma unroll
    for (int k = 0; k < 4; k++) acc += th[lane + 32 * k] * fcw[lane + 32 * k];
    #pragma unroll
    for (int s = 16; s > 0; s >>= 1) acc += __shfl_down_sync(0xFFFFFFFFu, acc, s);
    if (lane == 0) out[warp] = sigt(acc + fcb[0]);
}

// ---------------- launcher: kernel launches ONLY ----------------
extern "C" void kernel_launch(void* const* d_in, const int* in_sizes, int n_in,
                              void* d_out, int out_size) {
    const int*   diag = (const int*)d_in[0];
    const float* mask = (const float*)d_in[1];
    const float* tab  = (const float*)d_in[2];
    const float* Wih  = (const float*)d_in[3];
    const float* Whh  = (const float*)d_in[4];
    const float* bih  = (const float*)d_in[5];
    const float* bhh  = (const float*)d_in[6];
    const float* fcw  = (const float*)d_in[7];
    const float* fcb  = (const float*)d_in[8];
    float* out = (float*)d_out;

    (void)in_sizes; (void)n_in; (void)out_size;

    k_last<<<B, 128>>>(mask);
    k_embed<<<(B * V) / 8, 256>>>(diag, mask, tab);
    k_gemm<<<dim3(M_TOT / BMg, G4 / BNg), 256>>>(Wih, bih, bhh);
    k_rec<<<E, 416>>>(Whh);
    k_fc<<<32, 256>>>(fcw, fcb, out);
}